// round 14
// baseline (speedup 1.0000x reference)
#include <cuda_runtime.h>
#include <cuda_fp16.h>
#include <cstdint>
#include <cstddef>

// ===================== portable tensor-core helpers (sm_80+) ================
__device__ __forceinline__ uint32_t smem_u32(const void* p) {
    uint32_t a;
    asm("{ .reg .u64 t; cvta.to.shared.u64 t, %1; cvt.u32.u64 %0, t; }"
        : "=r"(a) : "l"(p));
    return a;
}
#define CP16(sm, gp) \
    asm volatile("cp.async.cg.shared.global [%0], [%1], 16;" :: "r"(sm), "l"(gp))
#define CP_COMMIT() asm volatile("cp.async.commit_group;" ::: "memory")
#define CP_WAIT(n)  asm volatile("cp.async.wait_group %0;" :: "n"(n) : "memory")

#define LDSM_X4(r0, r1, r2, r3, addr) \
    asm volatile("ldmatrix.sync.aligned.m8n8.x4.shared.b16 {%0,%1,%2,%3}, [%4];" \
                 : "=r"(r0), "=r"(r1), "=r"(r2), "=r"(r3) : "r"(addr))
#define MMA16816(c, a, b) \
    asm volatile("mma.sync.aligned.m16n8k16.row.col.f32.f16.f16.f32 " \
                 "{%0,%1,%2,%3}, {%4,%5,%6,%7}, {%8,%9}, {%0,%1,%2,%3};" \
                 : "+f"((c)[0]), "+f"((c)[1]), "+f"((c)[2]), "+f"((c)[3]) \
                 : "r"((a)[0]), "r"((a)[1]), "r"((a)[2]), "r"((a)[3]), \
                   "r"((b)[0]), "r"((b)[1]))

// ===================== scratch (fp16 operands, all single-rounded) ==========
__device__ uint4 g_P1[262144];   // P1 [2048][1024]
__device__ uint4 g_Wt[131072];   // Wt [1024][1024] (N-major)
__device__ uint4 g_Q1[262144];   // Q1 [32*1024][64]
__device__ uint4 g_R1[262144];   // R1 [16 he][2048 t][64]

// ===================== split kernels ========================================
__global__ void split_pq(const float* __restrict__ P,
                         const float* __restrict__ Q) {
    int idx = blockIdx.x * 256 + threadIdx.x;     // 2M total
    if (idx < 1048576) {                          // P: 2048 rows * 512 pairs
        int m = idx >> 9, kp = idx & 511;
        float2 v = make_float2(0.f, 0.f);
        if (m < 2047) v = *(const float2*)(P + (size_t)m * 1024 + 2 * kp);
        __half2 h;
        h.x = __float2half_rn(v.x); h.y = __float2half_rn(v.y);
        ((__half2*)g_P1)[(size_t)m * 512 + kp] = h;
    } else {                                      // Q: 32768 rows * 32 pairs
        int q = idx - 1048576;
        int gi = q >> 5, dp = q & 31;
        float2 v = *(const float2*)(Q + (size_t)gi * 64 + 2 * dp);
        __half2 h;
        h.x = __float2half_rn(v.x); h.y = __float2half_rn(v.y);
        ((__half2*)g_Q1)[(size_t)gi * 32 + dp] = h;
    }
}

__global__ void split_w(const float* __restrict__ W) {
    __shared__ float t[32][33];
    const int n0 = blockIdx.x * 32, k0 = blockIdx.y * 32;
    const int x = threadIdx.x, y = threadIdx.y;   // (32, 8)
    for (int r = 0; r < 32; r += 8)
        t[y + r][x] = W[(size_t)(k0 + y + r) * 1024 + n0 + x];
    __syncthreads();
    __half* Wt = (__half*)g_Wt;
    for (int r = 0; r < 32; r += 8) {
        const float v = t[x][y + r];              // W[k0+x][n0+y+r]
        const int n = n0 + y + r, k = k0 + x;
        Wt[(size_t)n * 1024 + k] = __float2half_rn(v);
    }
}

// ===================== warp-tile fragments (32x32 per warp per k16) =========
// 256 threads = 8 warps, 4(m) x 2(n) warp grid over a 128x64 tile.
struct Frag  { float c[2][4][4]; };               // accumulators [mi][ni][4]
struct KTile { uint32_t a[2][4]; uint32_t b[4][2]; };

template <int STRIDE>
__device__ __forceinline__ void ld_ktile(KTile& t, const __half* As,
                                         const __half* Bs,
                                         int wm, int wn, int lane, int k16) {
#pragma unroll
    for (int mi = 0; mi < 2; ++mi) {
        const uint32_t ad = smem_u32(
            As + (wm + mi * 16 + (lane & 15)) * STRIDE + k16 + ((lane >> 4) << 3));
        LDSM_X4(t.a[mi][0], t.a[mi][1], t.a[mi][2], t.a[mi][3], ad);
    }
#pragma unroll
    for (int nh = 0; nh < 2; ++nh) {
        uint32_t r0, r1, r2, r3;
        const uint32_t bd = smem_u32(
            Bs + (wn + nh * 16 + (lane & 15)) * STRIDE + k16 + ((lane >> 4) << 3));
        LDSM_X4(r0, r1, r2, r3, bd);
        t.b[nh * 2][0] = r0;     t.b[nh * 2][1] = r2;
        t.b[nh * 2 + 1][0] = r1; t.b[nh * 2 + 1][1] = r3;
    }
}

__device__ __forceinline__ void mma_ktile(const KTile& t, Frag& f) {
#pragma unroll
    for (int mi = 0; mi < 2; ++mi)
#pragma unroll
        for (int ni = 0; ni < 4; ++ni)
            MMA16816(f.c[mi][ni], t.a[mi], t.b[ni]);
}

// B-only fragment load (Q fragments are register-resident in gemm2)
template <int STRIDE>
__device__ __forceinline__ void ld_bfrag(uint32_t b[4][2], const __half* Bs,
                                         int wn, int lane, int k16) {
#pragma unroll
    for (int nh = 0; nh < 2; ++nh) {
        uint32_t r0, r1, r2, r3;
        const uint32_t bd = smem_u32(
            Bs + (wn + nh * 16 + (lane & 15)) * STRIDE + k16 + ((lane >> 4) << 3));
        LDSM_X4(r0, r1, r2, r3, bd);
        b[nh * 2][0] = r0;     b[nh * 2][1] = r2;
        b[nh * 2 + 1][0] = r1; b[nh * 2 + 1][1] = r3;
    }
}

__device__ __forceinline__ void mma_qb(const uint32_t a[2][4],
                                       const uint32_t b[4][2], Frag& f) {
#pragma unroll
    for (int mi = 0; mi < 2; ++mi)
#pragma unroll
        for (int ni = 0; ni < 4; ++ni)
            MMA16816(f.c[mi][ni], a[mi], b[ni]);
}

// ===================== GEMM1: R = P1 @ W1  (M=2048,N=1024,K=1024) ===========
#define G1_STRIDE 72
#define G1_A_ELEMS (128 * G1_STRIDE)
#define G1_B_ELEMS (64 * G1_STRIDE)
#define G1_STAGE_ELEMS (G1_A_ELEMS + G1_B_ELEMS)
#define G1_STAGE_BYTES (G1_STAGE_ELEMS * 2)

__global__ __launch_bounds__(256) void gemm1_mma() {
    extern __shared__ __half sm[];
    const int tid = threadIdx.x, lane = tid & 31, wid = tid >> 5;
    const int wm = (wid >> 1) << 5, wn = (wid & 1) << 5;
    const int m0 = blockIdx.y << 7, n0 = blockIdx.x << 6;

    const __half* Ag = (const __half*)g_P1 + (size_t)m0 * 1024;
    const __half* Bg = (const __half*)g_Wt + (size_t)n0 * 1024;
    __half* Rc = (__half*)g_R1;

    const uint32_t smA = smem_u32(sm);

#define G1_LOAD_STAGE(slot, kglob)                                            \
    do {                                                                      \
        const uint32_t _sb = smA + (uint32_t)(slot) * G1_STAGE_BYTES;         \
        _Pragma("unroll")                                                     \
        for (int r = 0; r < 4; ++r) {                                         \
            const int idx = r * 256 + tid;                                    \
            const int row = idx >> 3, ko = (idx & 7) << 3;                    \
            CP16(_sb + (uint32_t)(row * G1_STRIDE + ko) * 2,                  \
                 Ag + (size_t)row * 1024 + (kglob) + ko);                     \
        }                                                                     \
        _Pragma("unroll")                                                     \
        for (int r = 0; r < 2; ++r) {                                         \
            const int idx = r * 256 + tid;                                    \
            const int row = idx >> 3, ko = (idx & 7) << 3;                    \
            CP16(_sb + (uint32_t)(G1_A_ELEMS + row * G1_STRIDE + ko) * 2,     \
                 Bg + (size_t)row * 1024 + (kglob) + ko);                     \
        }                                                                     \
    } while (0)

    const int NK = 16;
    G1_LOAD_STAGE(0, 0);   CP_COMMIT();
    G1_LOAD_STAGE(1, 64);  CP_COMMIT();

    Frag f;
#pragma unroll
    for (int mi = 0; mi < 2; ++mi)
#pragma unroll
        for (int ni = 0; ni < 4; ++ni)
#pragma unroll
            for (int r = 0; r < 4; ++r) f.c[mi][ni][r] = 0.f;

    int rs = 0, ws = 2;
    for (int kk = 0; kk < NK; ++kk) {
        CP_WAIT(1);
        __syncthreads();
        if (kk + 2 < NK) G1_LOAD_STAGE(ws, (kk + 2) * 64);
        CP_COMMIT();
        const __half* As = sm + rs * G1_STAGE_ELEMS;
        const __half* Bs = As + G1_A_ELEMS;
        KTile t0, t1;
        ld_ktile<G1_STRIDE>(t0, As, Bs, wm, wn, lane, 0);
        ld_ktile<G1_STRIDE>(t1, As, Bs, wm, wn, lane, 16);
        mma_ktile(t0, f);
        ld_ktile<G1_STRIDE>(t0, As, Bs, wm, wn, lane, 32);
        mma_ktile(t1, f);
        ld_ktile<G1_STRIDE>(t1, As, Bs, wm, wn, lane, 48);
        mma_ktile(t0, f);
        mma_ktile(t1, f);
        rs = rs == 2 ? 0 : rs + 1;
        ws = ws == 2 ? 0 : ws + 1;
    }

    // epilogue: fp32 accum -> fp16 -> R1[he][m][d]
#pragma unroll
    for (int mi = 0; mi < 2; ++mi)
#pragma unroll
        for (int ni = 0; ni < 4; ++ni)
#pragma unroll
            for (int r = 0; r < 2; ++r) {
                const int m = m0 + wm + mi * 16 + (lane >> 2) + r * 8;
                const int n = n0 + wn + ni * 8 + ((lane & 3) << 1);
                __half2 h;
                h.x = __float2half_rn(f.c[mi][ni][r * 2]);
                h.y = __float2half_rn(f.c[mi][ni][r * 2 + 1]);
                const int he = n >> 6, d = n & 63;
                *(__half2*)(Rc + ((size_t)(he * 2048 + m)) * 64 + d) = h;
            }
}

// ===================== GEMM2: persistent-c banded score =====================
// out[g, i, i+c] = sum_d Q1[g,i,d] . R1[he, 1023+c, d]   (K=64)
// Grid 8(i-tile) x 32(g) = 256 CTAs. Q tile loaded ONCE, its 4 k-slice
// fragments hoisted to registers. 18 c-subtiles of 64, double-buffered R ring;
// subtile stores overlap future R loads.
#define G2_STRIDE 72
#define G2_Q_ELEMS (128 * G2_STRIDE)      // 9216 halfs (18432 B)
#define G2_R_ELEMS (64 * G2_STRIDE)       // 4608 halfs (9216 B) per slot
#define G2_STG_OFF (G2_Q_ELEMS + 2 * G2_R_ELEMS)   // in halfs
#define G2_STG_STRIDE 66                  // floats per staged row
#define G2_SMEM_BYTES (G2_STG_OFF * 2 + 128 * G2_STG_STRIDE * 4)  // 70656

__global__ __launch_bounds__(256) void gemm2_mma(float* __restrict__ out) {
    extern __shared__ __half sm[];
    const int tid = threadIdx.x, lane = tid & 31, wid = tid >> 5;
    const int wm = (wid >> 1) << 5, wn = (wid & 1) << 5;
    const int g = blockIdx.y, he = g >> 1;
    const int i0 = blockIdx.x << 7;

    const __half* Ag = (const __half*)g_Q1 + ((size_t)(g << 10) + i0) * 64;
    const __half* Bg = (const __half*)g_R1 + (size_t)he * 2048 * 64;

    const uint32_t smA = smem_u32(sm);
    const uint32_t smR = smA + G2_Q_ELEMS * 2;

    // R subtile loader: 64 rows x 64 d into slot, rows clamped (clamped rows
    // feed only never-stored columns)
#define G2_LOAD_R(slot, sidx)                                                 \
    do {                                                                      \
        const int _t0 = 895 - i0 + (sidx) * 64;                               \
        _Pragma("unroll")                                                     \
        for (int r = 0; r < 2; ++r) {                                         \
            const int idx = r * 256 + tid;                                    \
            const int row = idx >> 3, ko = (idx & 7) << 3;                    \
            int t = _t0 + row;                                                \
            t = t < 0 ? 0 : (t > 2046 ? 2046 : t);                            \
            CP16(smR + (uint32_t)(slot) * (G2_R_ELEMS * 2) +                  \
                     (uint32_t)(row * G2_STRIDE + ko) * 2,                    \
                 Bg + (size_t)t * 64 + ko);                                   \
        }                                                                     \
    } while (0)

    // prologue: Q tile + R[0] (group A), R[1] (group B)
#pragma unroll
    for (int r = 0; r < 4; ++r) {
        const int idx = r * 256 + tid;
        const int row = idx >> 3, ko = (idx & 7) << 3;
        CP16(smA + (uint32_t)(row * G2_STRIDE + ko) * 2,
             Ag + (size_t)row * 64 + ko);
    }
    G2_LOAD_R(0, 0);
    CP_COMMIT();
    G2_LOAD_R(1, 1);
    CP_COMMIT();

    CP_WAIT(1);                  // Q + R[0] landed
    __syncthreads();

    // hoist Q fragments: 4 k-slices x 2 m-frags, register-resident
    uint32_t qa[4][2][4];
#pragma unroll
    for (int ks = 0; ks < 4; ++ks)
#pragma unroll
        for (int mi = 0; mi < 2; ++mi) {
            const uint32_t ad = smem_u32(
                sm + (wm + mi * 16 + (lane & 15)) * G2_STRIDE + (ks << 4) +
                ((lane >> 4) << 3));
            LDSM_X4(qa[ks][mi][0], qa[ks][mi][1], qa[ks][mi][2], qa[ks][mi][3], ad);
        }

    float* Sf = (float*)(sm + G2_STG_OFF);
    float* og = out + ((size_t)g << 20);

#pragma unroll 1
    for (int s = 0; s < 18; ++s) {
        if (s) { CP_WAIT(1); __syncthreads(); }   // R[s] landed, staging free

        const __half* Bs = sm + G2_Q_ELEMS + (s & 1) * G2_R_ELEMS;
        Frag f;
#pragma unroll
        for (int mi = 0; mi < 2; ++mi)
#pragma unroll
            for (int ni = 0; ni < 4; ++ni)
#pragma unroll
                for (int r = 0; r < 4; ++r) f.c[mi][ni][r] = 0.f;

        uint32_t b0[4][2], b1[4][2];
        ld_bfrag<G2_STRIDE>(b0, Bs, wn, lane, 0);
        ld_bfrag<G2_STRIDE>(b1, Bs, wn, lane, 16);
        mma_qb(qa[0], b0, f);
        ld_bfrag<G2_STRIDE>(b0, Bs, wn, lane, 32);
        mma_qb(qa[1], b1, f);
        ld_bfrag<G2_STRIDE>(b1, Bs, wn, lane, 48);
        mma_qb(qa[2], b0, f);
        mma_qb(qa[3], b1, f);

        __syncthreads();                 // all reads of R slot done
        if (s + 2 < 18) G2_LOAD_R(s & 1, s + 2);
        CP_COMMIT();                     // unconditional: keeps numbering

        // stage accumulators
#pragma unroll
        for (int mi = 0; mi < 2; ++mi)
#pragma unroll
            for (int ni = 0; ni < 4; ++ni)
#pragma unroll
                for (int r = 0; r < 2; ++r) {
                    const int row = wm + mi * 16 + (lane >> 2) + r * 8;
                    const int col = wn + ni * 8 + ((lane & 3) << 1);
                    *(float2*)&Sf[row * G2_STG_STRIDE + col] =
                        make_float2(f.c[mi][ni][r * 2], f.c[mi][ni][r * 2 + 1]);
                }
        __syncthreads();

        // coalesced guarded row stores; j = i + c
        const int c0 = s * 64 - i0 - 128;
#pragma unroll
        for (int rr = 0; rr < 16; ++rr) {
            const int row = (wid << 4) + rr;
            const int i = i0 + row;
            float* orow = og + ((size_t)i << 10);
            const int j0 = i + c0 + (lane << 1);
            const float2 v = *(const float2*)&Sf[row * G2_STG_STRIDE + (lane << 1)];
            if (((i + c0) & 1) == 0) {
                if ((unsigned)j0 < 1023u) {
                    *(float2*)&orow[j0] = v;
                } else {
                    if ((unsigned)j0 < 1024u)       orow[j0] = v.x;
                    if ((unsigned)(j0 + 1) < 1024u) orow[j0 + 1] = v.y;
                }
            } else {
                if ((unsigned)j0 < 1024u)       orow[j0] = v.x;
                if ((unsigned)(j0 + 1) < 1024u) orow[j0 + 1] = v.y;
            }
        }
    }
}

// ===================== launch ===============================================
extern "C" void kernel_launch(void* const* d_in, const int* in_sizes, int n_in,
                              void* d_out, int out_size) {
    const float* query = (const float*)d_in[0];
    const float* posem = (const float*)d_in[1];
    const float* dense = (const float*)d_in[2];
    float* out = (float*)d_out;
    (void)in_sizes; (void)n_in; (void)out_size;

    cudaFuncSetAttribute(gemm1_mma, cudaFuncAttributeMaxDynamicSharedMemorySize,
                         3 * G1_STAGE_BYTES);
    cudaFuncSetAttribute(gemm2_mma, cudaFuncAttributeMaxDynamicSharedMemorySize,
                         G2_SMEM_BYTES);

    split_pq<<<8192, 256>>>(posem, query);
    split_w<<<dim3(32, 32), dim3(32, 8)>>>(dense);
    gemm1_mma<<<dim3(16, 16), 256, 3 * G1_STAGE_BYTES>>>();
    gemm2_mma<<<dim3(8, 32), 256, G2_SMEM_BYTES>>>(out);
}